// round 14
// baseline (speedup 1.0000x reference)
#include <cuda_runtime.h>
#include <cstdint>

// Problem constants
#define BB 4096
#define DD 256
#define HH 1024
#define NPROBE 10
#define STAGE_ELEMS (NPROBE * BB * DD)   // 10,485,760 per stage

#define JAX_PARTITIONABLE 1

typedef unsigned long long ull;

// ---------------- f32x2 packed helpers ----------------
__device__ __forceinline__ ull fma2(ull a, ull b, ull c) {
  ull d;
  asm("fma.rn.f32x2 %0, %1, %2, %3;" : "=l"(d) : "l"(a), "l"(b), "l"(c));
  return d;
}
__device__ __forceinline__ ull dup2(float x) {
  ull d;
  asm("mov.b64 %0, {%1, %1};" : "=l"(d) : "f"(x));
  return d;
}
__device__ __forceinline__ float2 unpk(ull a) {
  float2 f;
  asm("mov.b64 {%0, %1}, %2;" : "=f"(f.x), "=f"(f.y) : "l"(a));
  return f;
}

// ---------------- device scratch ----------------
__device__ float g_E[4ull * STAGE_ELEMS];     // 167.8 MB rademacher probes
__device__ float g_h[(size_t)BB * HH];
__device__ float g_z[(size_t)BB * DD];
__device__ float g_facc[(size_t)BB * DD];
__device__ float g_divpart[(size_t)BB * 16];

// ---------------- threefry2x32 (exact JAX semantics) ----------------
__device__ __forceinline__ void tf2x32(uint32_t k0, uint32_t k1,
                                       uint32_t x0, uint32_t x1,
                                       uint32_t& o0, uint32_t& o1) {
  uint32_t ks2 = k0 ^ k1 ^ 0x1BD11BDAu;
  x0 += k0; x1 += k1;
#define TFR(r) { x0 += x1; x1 = (x1 << (r)) | (x1 >> (32 - (r))); x1 ^= x0; }
  TFR(13) TFR(15) TFR(26) TFR(6)   x0 += k1;  x1 += ks2 + 1u;
  TFR(17) TFR(29) TFR(16) TFR(24)  x0 += ks2; x1 += k0 + 2u;
  TFR(13) TFR(15) TFR(26) TFR(6)   x0 += k0;  x1 += k1 + 3u;
  TFR(17) TFR(29) TFR(16) TFR(24)  x0 += k1;  x1 += ks2 + 4u;
  TFR(13) TFR(15) TFR(26) TFR(6)   x0 += ks2; x1 += k0 + 5u;
#undef TFR
  o0 = x0; o1 = x1;
}

__global__ void gen_kernel() {
  int stage = blockIdx.y;
  __shared__ uint32_t skey[2];
  if (threadIdx.x == 0) {
    uint32_t a0, a1, c0, c1;
    tf2x32(0u, 42u, 0u, (uint32_t)stage, a0, a1);   // fold_in
#if JAX_PARTITIONABLE
    tf2x32(a0, a1, 0u, 1u, c0, c1);                 // fold-like split, key[1]
#else
    uint32_t u0, u1, v0, v1;
    tf2x32(a0, a1, 0u, 2u, u0, u1);
    tf2x32(a0, a1, 1u, 3u, v0, v1);
    c0 = u1; c1 = v1;
#endif
    skey[0] = c0; skey[1] = c1;
  }
  __syncthreads();
  uint32_t c0 = skey[0], c1 = skey[1];
  unsigned j = blockIdx.x * 256u + threadIdx.x;
  uint32_t bit;
#if JAX_PARTITIONABLE
  uint32_t w0, w1;
  tf2x32(c0, c1, 0u, j, w0, w1);
  bit = (w0 ^ w1) & 1u;
#else
  const unsigned HALF = STAGE_ELEMS / 2u;
  uint32_t w0, w1;
  if (j < HALF) { tf2x32(c0, c1, j, j + HALF, w0, w1); bit = w0 & 1u; }
  else          { tf2x32(c0, c1, j - HALF, j, w0, w1); bit = w1 & 1u; }
#endif
  g_E[(size_t)stage * STAGE_ELEMS + j] = bit ? 1.0f : -1.0f;
}

// ---------------- fwd1: h = tanh(z @ W1[:256] + t*W1[256] + b1), f32x2 ----------------
// M=4096, N=1024, K=256. BM=BN=64, BK=16, 256 threads, 4x4 micro-tile via FMA2.
__global__ __launch_bounds__(256) void fwd1_kernel(const float* __restrict__ X,
                                                   const float* __restrict__ W1,
                                                   const float* __restrict__ b1,
                                                   float t, int useX) {
  __shared__ float sAd[16][140];   // duplicated A: sAd[c][2m],[2m+1] (pad 140 -> 16B align)
  __shared__ float sB[16][64];
  const float* Z = useX ? X : g_z;
  int m0 = blockIdx.y * 64, n0 = blockIdx.x * 64;
  int tid = threadIdx.x;
  int ty = tid >> 4, tx = tid & 15;
  int arow = tid >> 2;            // 0..63
  int acol = (tid & 3) * 4;       // 0,4,8,12
  int brow = tid >> 4;            // 0..15
  int bcol = (tid & 15) * 4;      // 0..60
  ull acc2[4][2];
#pragma unroll
  for (int i = 0; i < 4; ++i) { acc2[i][0] = 0ull; acc2[i][1] = 0ull; }

  for (int kk = 0; kk < DD; kk += 16) {
    float4 av = *(const float4*)&Z[(size_t)(m0 + arow) * DD + kk + acol];
    float4 bv = *(const float4*)&W1[(size_t)(kk + brow) * HH + n0 + bcol];
    __syncthreads();
    *(ull*)&sAd[acol + 0][2 * arow] = dup2(av.x);
    *(ull*)&sAd[acol + 1][2 * arow] = dup2(av.y);
    *(ull*)&sAd[acol + 2][2 * arow] = dup2(av.z);
    *(ull*)&sAd[acol + 3][2 * arow] = dup2(av.w);
    *(float4*)&sB[brow][bcol] = bv;
    __syncthreads();
#pragma unroll
    for (int c = 0; c < 16; ++c) {
      ulonglong2 aLo = *(const ulonglong2*)&sAd[c][8 * ty];       // {a0,a0},{a1,a1}
      ulonglong2 aHi = *(const ulonglong2*)&sAd[c][8 * ty + 4];   // {a2,a2},{a3,a3}
      ulonglong2 bp  = *(const ulonglong2*)&sB[c][tx * 4];        // {b0,b1},{b2,b3}
      acc2[0][0] = fma2(aLo.x, bp.x, acc2[0][0]);
      acc2[0][1] = fma2(aLo.x, bp.y, acc2[0][1]);
      acc2[1][0] = fma2(aLo.y, bp.x, acc2[1][0]);
      acc2[1][1] = fma2(aLo.y, bp.y, acc2[1][1]);
      acc2[2][0] = fma2(aHi.x, bp.x, acc2[2][0]);
      acc2[2][1] = fma2(aHi.x, bp.y, acc2[2][1]);
      acc2[3][0] = fma2(aHi.y, bp.x, acc2[3][0]);
      acc2[3][1] = fma2(aHi.y, bp.y, acc2[3][1]);
    }
  }
#pragma unroll
  for (int i = 0; i < 4; ++i) {
    int m = m0 + ty * 4 + i;
    float2 s0 = unpk(acc2[i][0]);
    float2 s1 = unpk(acc2[i][1]);
    float vals[4] = {s0.x, s0.y, s1.x, s1.y};
#pragma unroll
    for (int j = 0; j < 4; ++j) {
      int n = n0 + tx * 4 + j;
      float u = vals[j] + t * W1[(size_t)DD * HH + n] + b1[n];
      g_h[(size_t)m * HH + n] = tanhf(u);
    }
  }
}

// ---------------- fwd2: f = h @ W2 + b2 + RK4 epilogue (latency-bound, 95us) ----------
__global__ __launch_bounds__(256) void fwd2_kernel(const float* __restrict__ X,
                                                   const float* __restrict__ W2,
                                                   const float* __restrict__ b2,
                                                   float wf, float cz, int first, int writez) {
  __shared__ float sA[16][68];
  __shared__ float sB[16][64];
  int m0 = blockIdx.y * 64, n0 = blockIdx.x * 64;
  int tid = threadIdx.x;
  int ty = tid >> 4, tx = tid & 15;
  int arow = tid >> 2;
  int acol = (tid & 3) * 4;
  int brow = tid >> 4;
  int bcol = (tid & 15) * 4;
  float acc[4][4] = {};
  for (int kk = 0; kk < HH; kk += 16) {
    float4 av = *(const float4*)&g_h[(size_t)(m0 + arow) * HH + kk + acol];
    float4 bv = *(const float4*)&W2[(size_t)(kk + brow) * DD + n0 + bcol];
    __syncthreads();
    sA[acol + 0][arow] = av.x; sA[acol + 1][arow] = av.y;
    sA[acol + 2][arow] = av.z; sA[acol + 3][arow] = av.w;
    *(float4*)&sB[brow][bcol] = bv;
    __syncthreads();
#pragma unroll
    for (int c = 0; c < 16; ++c) {
      float4 a = *(const float4*)&sA[c][ty * 4];
      float4 b = *(const float4*)&sB[c][tx * 4];
      float aa[4] = {a.x, a.y, a.z, a.w};
      float bb[4] = {b.x, b.y, b.z, b.w};
#pragma unroll
      for (int i = 0; i < 4; ++i)
#pragma unroll
        for (int j = 0; j < 4; ++j)
          acc[i][j] += aa[i] * bb[j];
    }
  }
#pragma unroll
  for (int i = 0; i < 4; ++i)
#pragma unroll
    for (int j = 0; j < 4; ++j) {
      int m = m0 + ty * 4 + i, n = n0 + tx * 4 + j;
      float f = acc[i][j] + b2[n];
      size_t idx = (size_t)m * DD + n;
      float fa = wf * f;
      if (first) g_facc[idx] = fa; else g_facc[idx] += fa;
      if (writez) g_z[idx] = X[idx] + cz * f;
    }
}

// ---------------- probe kernel (f32x2 dual-GEMM) ----------------
// Tile 64(b) x 64(k). W1/W2 slabs resident for ALL 256 c (padded rows of 68).
// E duplicated in smem, c-chunked (128 c x 128 dup floats), register-prefetched.
// smem: 2*256*68*4 + 128*128*4 = 204,800 B. 256 threads, micro-tile 4bi x 4kj dual.
__global__ __launch_bounds__(256, 1) void probe_kernel(const float* __restrict__ W1,
                                                       const float* __restrict__ W2,
                                                       int stage, float wstage, int first) {
  extern __shared__ float sm[];
  float* sW1 = sm;                 // [256][68] : sW1[c*68 + kk] = W1[c, k0+kk]
  float* sW2 = sm + 256 * 68;      // [256][68] : sW2[c*68 + kk] = W2[k0+kk, c]
  float* sEd = sm + 2 * 256 * 68;  // [128][128]: sEd[cc*128 + 2b(+1)] = E dup (c-chunk)
  int k0 = blockIdx.x * 64;
  int b0 = blockIdx.y * 64;
  int tid = threadIdx.x;
  int tx = tid & 15, ty = tid >> 4;

  // ---- W1 slab: vectorized ----
#pragma unroll
  for (int j = 0; j < 16; ++j) {
    int f = j * 256 + tid;           // float4 index 0..4095
    int c = f >> 4;
    int kq = (f & 15) * 4;
    *(float4*)&sW1[c * 68 + kq] = *(const float4*)&W1[(size_t)c * HH + k0 + kq];
  }
  // ---- W2 slab transposed: sW2[c][k] = W2[k0+k, c] ----
  for (int r = 0; r < 64; ++r)
    sW2[tid * 68 + r] = W2[(size_t)(k0 + r) * DD + tid];

  // E fill thread mapping: rE = row within b-slab, cqE selects c sub-column
  int rE = tid >> 2;          // 0..63
  int cqE = tid & 3;          // 0..3
  const float* Ebase = g_E + (size_t)stage * STAGE_ELEMS + (size_t)b0 * DD;

  ull S2[4][2];
#pragma unroll
  for (int i = 0; i < 4; ++i) { S2[i][0] = 0ull; S2[i][1] = 0ull; }

  // prefetch chunk 0 of probe 0
  float4 pf[8];
  {
    const float* Ep = Ebase;   // probe 0, chunk 0
#pragma unroll
    for (int j = 0; j < 8; ++j)
      pf[j] = *(const float4*)&Ep[(size_t)rE * DD + cqE * 32 + j * 4];
  }

  ull v2[4][2], w2[4][2];
  for (int pc = 0; pc < 2 * NPROBE; ++pc) {
    int ch = pc & 1;
    __syncthreads();       // previous readers of sEd done
    // store duplicated E chunk
#pragma unroll
    for (int j = 0; j < 8; ++j) {
      float4 e = pf[j];
      int cc = cqE * 32 + j * 4;
      *(ull*)&sEd[(cc + 0) * 128 + 2 * rE] = dup2(e.x);
      *(ull*)&sEd[(cc + 1) * 128 + 2 * rE] = dup2(e.y);
      *(ull*)&sEd[(cc + 2) * 128 + 2 * rE] = dup2(e.z);
      *(ull*)&sEd[(cc + 3) * 128 + 2 * rE] = dup2(e.w);
    }
    // prefetch next chunk (hidden under compute)
    if (pc + 1 < 2 * NPROBE) {
      int np = (pc + 1) >> 1, nch = (pc + 1) & 1;
      const float* Ep = Ebase + (size_t)np * BB * DD + nch * 128;
#pragma unroll
      for (int j = 0; j < 8; ++j)
        pf[j] = *(const float4*)&Ep[(size_t)rE * DD + cqE * 32 + j * 4];
    }
    __syncthreads();

    if (ch == 0) {
#pragma unroll
      for (int i = 0; i < 4; ++i) {
        v2[i][0] = 0ull; v2[i][1] = 0ull;
        w2[i][0] = 0ull; w2[i][1] = 0ull;
      }
    }
    int cbase = ch * 128;
#pragma unroll 4
    for (int cc = 0; cc < 128; ++cc) {
      ulonglong2 aLo = *(const ulonglong2*)&sEd[cc * 128 + 8 * ty];      // {a0,a0},{a1,a1}
      ulonglong2 aHi = *(const ulonglong2*)&sEd[cc * 128 + 8 * ty + 4];  // {a2,a2},{a3,a3}
      ulonglong2 pp = *(const ulonglong2*)&sW1[(cbase + cc) * 68 + tx * 4]; // {p0,p1},{p2,p3}
      ulonglong2 qq = *(const ulonglong2*)&sW2[(cbase + cc) * 68 + tx * 4];
      v2[0][0] = fma2(aLo.x, pp.x, v2[0][0]);
      v2[0][1] = fma2(aLo.x, pp.y, v2[0][1]);
      v2[1][0] = fma2(aLo.y, pp.x, v2[1][0]);
      v2[1][1] = fma2(aLo.y, pp.y, v2[1][1]);
      v2[2][0] = fma2(aHi.x, pp.x, v2[2][0]);
      v2[2][1] = fma2(aHi.x, pp.y, v2[2][1]);
      v2[3][0] = fma2(aHi.y, pp.x, v2[3][0]);
      v2[3][1] = fma2(aHi.y, pp.y, v2[3][1]);
      w2[0][0] = fma2(aLo.x, qq.x, w2[0][0]);
      w2[0][1] = fma2(aLo.x, qq.y, w2[0][1]);
      w2[1][0] = fma2(aLo.y, qq.x, w2[1][0]);
      w2[1][1] = fma2(aLo.y, qq.y, w2[1][1]);
      w2[2][0] = fma2(aHi.x, qq.x, w2[2][0]);
      w2[2][1] = fma2(aHi.x, qq.y, w2[2][1]);
      w2[3][0] = fma2(aHi.y, qq.x, w2[3][0]);
      w2[3][1] = fma2(aHi.y, qq.y, w2[3][1]);
    }
    if (ch == 1) {   // end of probe: fold S += v .* w (elementwise packed)
#pragma unroll
      for (int i = 0; i < 4; ++i) {
        S2[i][0] = fma2(v2[i][0], w2[i][0], S2[i][0]);
        S2[i][1] = fma2(v2[i][1], w2[i][1], S2[i][1]);
      }
    }
  }

  // epilogue: weight by (1 - h^2), reduce over this block's 64 k's
  float part[4];
#pragma unroll
  for (int bi = 0; bi < 4; ++bi) {
    int b = b0 + ty * 4 + bi;
    float2 s0 = unpk(S2[bi][0]);
    float2 s1 = unpk(S2[bi][1]);
    const float* hp = &g_h[(size_t)b * HH + k0 + tx * 4];
    float h0 = hp[0], h1 = hp[1], h2 = hp[2], h3 = hp[3];
    part[bi] = s0.x * (1.f - h0 * h0) + s0.y * (1.f - h1 * h1) +
               s1.x * (1.f - h2 * h2) + s1.y * (1.f - h3 * h3);
  }
#pragma unroll
  for (int off = 8; off > 0; off >>= 1)
#pragma unroll
    for (int bi = 0; bi < 4; ++bi)
      part[bi] += __shfl_down_sync(0xFFFFFFFFu, part[bi], off, 16);
  if (tx == 0) {
#pragma unroll
    for (int bi = 0; bi < 4; ++bi) {
      int b = b0 + ty * 4 + bi;
      size_t idx = (size_t)b * 16 + blockIdx.x;
      float val = wstage * part[bi];
      if (first) g_divpart[idx] = val; else g_divpart[idx] += val;
    }
  }
}

// ---------------- final: assemble output (2, 4096, 257) ----------------
__global__ void final_kernel(const float* __restrict__ X, float* __restrict__ out) {
  int idx = blockIdx.x * blockDim.x + threadIdx.x;
  if (idx >= BB * 257) return;
  int b = idx / 257, c = idx % 257;
  float y0, y1;
  if (c < DD) {
    float xv = X[(size_t)b * DD + c];
    y0 = xv;
    y1 = xv + g_facc[(size_t)b * DD + c] * (1.0f / 6.0f);
  } else {
    y0 = 0.0f;
    float dacc = 0.f;
#pragma unroll
    for (int kb = 0; kb < 16; ++kb) dacc += g_divpart[(size_t)b * 16 + kb];
    y1 = -dacc * (1.0f / 60.0f);
  }
  out[idx] = y0;
  out[(size_t)BB * 257 + idx] = y1;
}

// ---------------- launch ----------------
extern "C" void kernel_launch(void* const* d_in, const int* in_sizes, int n_in,
                              void* d_out, int out_size) {
  const float* x  = (const float*)d_in[0];
  const float* W1 = (const float*)d_in[1];
  const float* b1 = (const float*)d_in[2];
  const float* W2 = (const float*)d_in[3];
  const float* b2 = (const float*)d_in[4];
  float* out = (float*)d_out;

  const int PROBE_SMEM = (2 * 256 * 68 + 128 * 128) * (int)sizeof(float);  // 204,800 B
  cudaFuncSetAttribute(probe_kernel, cudaFuncAttributeMaxDynamicSharedMemorySize, PROBE_SMEM);

  gen_kernel<<<dim3(STAGE_ELEMS / 256, 4), 256>>>();

  const float ts[4] = {0.0f, 0.5f, 0.5f, 1.0f};
  const float cz[4] = {0.5f, 0.5f, 1.0f, 0.0f};
  const float wf[4] = {1.0f, 2.0f, 2.0f, 1.0f};

  for (int s = 0; s < 4; ++s) {
    fwd1_kernel<<<dim3(HH / 64, BB / 64), 256>>>(x, W1, b1, ts[s], s == 0 ? 1 : 0);
    probe_kernel<<<dim3(HH / 64, BB / 64), 256, PROBE_SMEM>>>(W1, W2, s, wf[s], s == 0 ? 1 : 0);
    fwd2_kernel<<<dim3(DD / 64, BB / 64), 256>>>(x, W2, b2, wf[s], cz[s],
                                                 s == 0 ? 1 : 0, s < 3 ? 1 : 0);
  }

  final_kernel<<<(BB * 257 + 255) / 256, 256>>>(x, out);
}